// round 9
// baseline (speedup 1.0000x reference)
#include <cuda_runtime.h>
#include <cuda_fp16.h>
#include <cstdint>

#define BB 8
#define NN 2048
#define FF 256

// ---- scratch ----
__device__ unsigned short g_WhTh[BB * FF * NN];   // f16 hi, [b][f][j], 8 MB
__device__ unsigned short g_WtH[FF * FF];         // f16 W^T hi [fout][fin]
__device__ unsigned short g_WtL[FF * FF];         // f16 W^T lo
__device__ float g_s1[BB * NN];
__device__ float g_s2[BB * NN];
__device__ float g_smax[BB];
__device__ unsigned long long g_mask[NN * 32];

typedef unsigned long long ull;

// FFMA-only expf. Valid for x in [-80, 10], rel err ~3e-6.
__device__ __forceinline__ float fexp(float x) {
    const float L2E = 1.4426950408889634f;
    float t = fmaf(x, L2E, 12582912.0f);
    int   k = __float_as_int(t);
    float r = t - 12582912.0f;
    float f = fmaf(x, L2E, -r);
    float p = 1.33335581e-3f;
    p = fmaf(p, f, 9.61812910e-3f);
    p = fmaf(p, f, 5.55041086e-2f);
    p = fmaf(p, f, 2.40226507e-1f);
    p = fmaf(p, f, 6.93147182e-1f);
    p = fmaf(p, f, 1.0f);
    return __int_as_float(__float_as_int(p) + (k << 23));
}
__device__ __forceinline__ float elu1(float x) {
    return x > 0.f ? x : fexp(fmaxf(x, -80.f)) - 1.f;
}
__device__ __forceinline__ uint32_t packh2r(float a, float b, float& ra, float& rb) {
    __half ha = __float2half_rn(a), hb = __float2half_rn(b);
    ra = a - __half2float(ha);
    rb = b - __half2float(hb);
    __half2 h2 = __halves2half2(ha, hb);
    return reinterpret_cast<uint32_t&>(h2);
}
__device__ __forceinline__ uint32_t packh2(float a, float b) {
    __half2 h2 = __floats2half2_rn(a, b);
    return reinterpret_cast<uint32_t&>(h2);
}

#define SWZ128(o) ((o) ^ (((o) >> 3) & 0x70))

// ---- mma.sync / ldmatrix / cp.async ----
__device__ __forceinline__ void ldsm4(uint32_t* r, uint32_t a) {
    asm volatile("ldmatrix.sync.aligned.m8n8.x4.shared.b16 {%0,%1,%2,%3}, [%4];"
        : "=r"(r[0]), "=r"(r[1]), "=r"(r[2]), "=r"(r[3]) : "r"(a));
}
__device__ __forceinline__ void mmaf16(float* c, const uint32_t* a, const uint32_t* b) {
    asm volatile(
        "mma.sync.aligned.m16n8k16.row.col.f32.f16.f16.f32 "
        "{%0,%1,%2,%3}, {%4,%5,%6,%7}, {%8,%9}, {%0,%1,%2,%3};"
        : "+f"(c[0]), "+f"(c[1]), "+f"(c[2]), "+f"(c[3])
        : "r"(a[0]), "r"(a[1]), "r"(a[2]), "r"(a[3]), "r"(b[0]), "r"(b[1]));
}
__device__ __forceinline__ uint32_t smem_u32(const void* p) {
    uint32_t a;
    asm("{ .reg .u64 t; cvta.to.shared.u64 t, %1; cvt.u32.u64 %0, t; }"
        : "=r"(a) : "l"(p));
    return a;
}
#define CPA16(dst, src) asm volatile( \
    "cp.async.cg.shared.global [%0], [%1], 16;" :: "r"(dst), "l"(src))
#define CPCOMMIT() asm volatile("cp.async.commit_group;" ::: "memory")
#define CPWAIT1() asm volatile("cp.async.wait_group 1;" ::: "memory")
#define CPWAIT0() asm volatile("cp.async.wait_group 0;" ::: "memory")

// ========================================================================
// Kernel 0: pack W -> f16 hi/lo, transposed [fout][fin]
// ========================================================================
__global__ void k_packW(const float* __restrict__ W) {
    const int fo = blockIdx.x, fi = threadIdx.x;
    float v = W[fi * FF + fo];
    float r0, dummy;
    uint32_t hp = packh2r(v, 0.f, r0, dummy);
    g_WtH[fo * FF + fi] = (unsigned short)(hp & 0xffff);
    g_WtL[fo * FF + fi] = (unsigned short)(packh2(r0, 0.f) & 0xffff);
}

// ========================================================================
// Kernel 1: pack mask bits + zero s1/s2
// ========================================================================
__global__ void __launch_bounds__(256)
k_mask(const int* __restrict__ adj) {
    const int gid = blockIdx.x * 256 + threadIdx.x;
    if (gid < BB * NN) { g_s1[gid] = 0.f; g_s2[gid] = 0.f; }
    const int i = gid >> 7, seg = gid & 127;
    const int4* src = (const int4*)(adj + (size_t)i * NN + seg * 16);
    unsigned int m = 0;
#pragma unroll
    for (int q = 0; q < 4; ++q) {
        int4 v = src[q];
        if (v.x > 0) m |= 1u << (q * 4 + 0);
        if (v.y > 0) m |= 1u << (q * 4 + 1);
        if (v.z > 0) m |= 1u << (q * 4 + 2);
        if (v.w > 0) m |= 1u << (q * 4 + 3);
    }
    int d = i - seg * 16;
    if (d >= 0 && d < 16) m |= 1u << d;
    ((unsigned short*)g_mask)[gid] = (unsigned short)m;
}

// ========================================================================
// Kernel 2 (mma): Wh = h @ W (3-term f16 split, fp32-accurate).
// ========================================================================
#define G_AH 0
#define G_AL 16384
#define G_BH 32768
#define G_BL 49152

__global__ void __launch_bounds__(256)
k_gemm1(const float* __restrict__ h, const float* __restrict__ a) {
    extern __shared__ __align__(1024) char sm[];
    const uint32_t smb = smem_u32(sm);
    __shared__ float as1[128], as2[128];
    const int i0g = blockIdx.x * 128, fy = blockIdx.y;
    const int b = i0g >> 11, jb = i0g & (NN - 1);
    const int t = threadIdx.x, wid = t >> 5, lane = t & 31;
    const int wm = wid & 3, wn = wid >> 2;

    if (t < 128) as1[t] = a[fy * 128 + t];
    else         as2[t - 128] = a[256 + fy * 128 + (t - 128)];

    const uint32_t a_l = (uint32_t)(((wm * 32 + (lane & 15)) << 7) | ((lane >> 4) << 4));
    const uint32_t b_l = (uint32_t)(((wn * 64 + ((lane >> 4) << 3) + (lane & 7)) << 7)
                                    | (((lane >> 3) & 1) << 4));

    float acc[2][8][4];
#pragma unroll
    for (int mt = 0; mt < 2; ++mt)
#pragma unroll
        for (int nt = 0; nt < 8; ++nt)
#pragma unroll
            for (int e = 0; e < 4; ++e) acc[mt][nt][e] = 0.f;

    const int arow = t >> 1, akh = t & 1;
    const float* hp = h + ((size_t)(i0g + arow)) * FF + akh * 32;

    for (int c = 0; c < 4; ++c) {
        const int k0 = c * 64;
#pragma unroll
        for (int q = 0; q < 4; ++q) {
            int idx = t + q * 256;
            int f = idx >> 3, seg = idx & 7;
            const unsigned short* sH = g_WtH + (size_t)(fy * 128 + f) * FF + k0 + seg * 8;
            const unsigned short* sL = g_WtL + (size_t)(fy * 128 + f) * FF + k0 + seg * 8;
            uint32_t soff = SWZ128((uint32_t)(f * 128 + seg * 16));
            CPA16(smb + G_BH + soff, sH);
            CPA16(smb + G_BL + soff, sL);
        }
        CPCOMMIT();
#pragma unroll
        for (int q = 0; q < 8; ++q) {
            float4 v = *(const float4*)(hp + k0 + q * 4);
            float r0, r1, r2, r3;
            uint32_t h01 = packh2r(v.x, v.y, r0, r1);
            uint32_t h23 = packh2r(v.z, v.w, r2, r3);
            uint32_t l01 = packh2(r0, r1);
            uint32_t l23 = packh2(r2, r3);
            uint32_t base = (uint32_t)(arow * 128 + (akh * 32 + q * 4) * 2);
            uint32_t so = SWZ128(base);
            *(uint2*)(sm + G_AH + so) = make_uint2(h01, h23);
            *(uint2*)(sm + G_AL + so) = make_uint2(l01, l23);
        }
        CPWAIT0();
        __syncthreads();

#pragma unroll
        for (int k16 = 0; k16 < 4; ++k16) {
            uint32_t ahh[2][4], ahl[2][4];
#pragma unroll
            for (int mt = 0; mt < 2; ++mt) {
                uint32_t ao = SWZ128(a_l + (uint32_t)(mt * 2048 + k16 * 32));
                ldsm4(ahh[mt], smb + G_AH + ao);
                ldsm4(ahl[mt], smb + G_AL + ao);
            }
#pragma unroll
            for (int nt2 = 0; nt2 < 4; ++nt2) {
                uint32_t bo = SWZ128(b_l + (uint32_t)(nt2 * 2048 + k16 * 32));
                uint32_t bh[4], bl[4];
                ldsm4(bh, smb + G_BH + bo);
                ldsm4(bl, smb + G_BL + bo);
#pragma unroll
                for (int mt = 0; mt < 2; ++mt) {
                    mmaf16(acc[mt][nt2 * 2 + 0], ahh[mt], bh);
                    mmaf16(acc[mt][nt2 * 2 + 1], ahh[mt], bh + 2);
                    mmaf16(acc[mt][nt2 * 2 + 0], ahl[mt], bh);
                    mmaf16(acc[mt][nt2 * 2 + 1], ahl[mt], bh + 2);
                    mmaf16(acc[mt][nt2 * 2 + 0], ahh[mt], bl);
                    mmaf16(acc[mt][nt2 * 2 + 1], ahh[mt], bl + 2);
                }
            }
        }
        __syncthreads();
    }

    // ---- epilogue: transpose via smem (fp32 [f][i], stride 130) ----
    float* ts = (float*)sm;
    const int tq = lane >> 2, tr = lane & 3;
#pragma unroll
    for (int mt = 0; mt < 2; ++mt) {
        int i_l = wm * 32 + mt * 16 + tq;
#pragma unroll
        for (int nt = 0; nt < 8; ++nt) {
            int f_l = wn * 64 + nt * 8 + tr * 2;
            ts[f_l * 130 + i_l]           = acc[mt][nt][0];
            ts[(f_l + 1) * 130 + i_l]     = acc[mt][nt][1];
            ts[f_l * 130 + i_l + 8]       = acc[mt][nt][2];
            ts[(f_l + 1) * 130 + i_l + 8] = acc[mt][nt][3];
        }
    }
    __syncthreads();

    {
        const int i_l = t >> 1, fh = t & 1;
        float s1p = 0.f, s2p = 0.f;
#pragma unroll 8
        for (int f = 0; f < 64; ++f) {
            int fl = fh * 64 + f;
            float v = ts[fl * 130 + i_l];
            s1p += v * as1[fl];
            s2p += v * as2[fl];
        }
        s1p += __shfl_xor_sync(0xffffffffu, s1p, 1);
        s2p += __shfl_xor_sync(0xffffffffu, s2p, 1);
        if (fh == 0) {
            atomicAdd(&g_s1[b * NN + jb + i_l], s1p);
            atomicAdd(&g_s2[b * NN + jb + i_l], s2p);
        }
    }

    {
        const int fl = t >> 1, half = t & 1;
        unsigned short* dst = g_WhTh + ((size_t)(b * FF) + fy * 128 + fl) * NN
                              + jb + half * 64;
        const float* src = ts + fl * 130 + half * 64;
#pragma unroll
        for (int q = 0; q < 8; ++q) {
            float v0 = src[q * 8 + 0], v1 = src[q * 8 + 1];
            float v2 = src[q * 8 + 2], v3 = src[q * 8 + 3];
            float v4 = src[q * 8 + 4], v5 = src[q * 8 + 5];
            float v6 = src[q * 8 + 6], v7 = src[q * 8 + 7];
            uint4 hv = make_uint4(packh2(v0, v1), packh2(v2, v3),
                                  packh2(v4, v5), packh2(v6, v7));
            *(uint4*)(dst + q * 8) = hv;
        }
    }
}

// ========================================================================
// Kernel 3: per-batch unmasked max of s2
// ========================================================================
__global__ void __launch_bounds__(256)
k_smax() {
    const int b = blockIdx.x, t = threadIdx.x;
    __shared__ float red[8];
    float mx = -3e38f;
#pragma unroll
    for (int q = 0; q < 8; ++q)
        mx = fmaxf(mx, g_s2[b * NN + t + q * 256]);
#pragma unroll
    for (int off = 16; off > 0; off >>= 1)
        mx = fmaxf(mx, __shfl_xor_sync(0xffffffffu, mx, off));
    if ((t & 31) == 0) red[t >> 5] = mx;
    __syncthreads();
    if (t == 0) {
        float v = red[0];
        for (int w = 1; w < 8; ++w) v = fmaxf(v, red[w]);
        g_smax[b] = v;
    }
}

// ========================================================================
// Kernel 4 (mma.sync f16): out = elu((P_u @ Wh) / Z), fused normalizer.
// CTA tile M=32 x N=256; 256 thr = 8 warps (2m x 4n); warp m16 x n64.
// j-chunks of 64; double-buffered 36 KB; 3 CTAs/SM target.
// ========================================================================
#define BUFSZ 36864
#define O_PH 0
#define O_BH 4096

__global__ void __launch_bounds__(256, 3)
k_attn(float* __restrict__ out) {
    extern __shared__ __align__(1024) char sm[];
    const uint32_t smb = smem_u32(sm);
    const int bz = blockIdx.y, i0 = blockIdx.x * 32;
    const int t = threadIdx.x, wid = t >> 5, lane = t & 31;
    const int wm = wid & 1, wn = wid >> 1;

    const int prow = t >> 3, jq = t & 7;          // 32 rows x 8 j per thread
    const float s1r = g_s1[bz * NN + i0 + prow];
    const float smax = g_smax[bz];
    float Mx = s1r + smax;
    const float Mi = fmaxf(Mx, 0.2f * Mx);
    const ull* mrow = g_mask + (size_t)(i0 + prow) * 32;

    const unsigned short* whH = g_WhTh + (size_t)bz * FF * NN;
    const float* s2B = g_s2 + bz * NN;

    const uint32_t a_l = (uint32_t)(((wm * 16 + (lane & 15)) << 7) | ((lane >> 4) << 4));
    const uint32_t b_l = (uint32_t)(((wn * 64 + ((lane >> 4) << 3) + (lane & 7)) << 7)
                                    | (((lane >> 3) & 1) << 4));

    float acc[8][4];
#pragma unroll
    for (int nt = 0; nt < 8; ++nt)
#pragma unroll
        for (int e = 0; e < 4; ++e) acc[nt][e] = 0.f;
    float zacc = 0.f;

    auto stageB = [&](int c, uint32_t bufa) {
        const int j0 = c * 64;
#pragma unroll
        for (int q = 0; q < 8; ++q) {
            int idx = t + q * 256;                 // 0..2047
            int f = idx >> 3, seg = idx & 7;
            size_t goff = (size_t)f * NN + j0 + seg * 8;
            uint32_t soff = SWZ128((uint32_t)(f * 128 + seg * 16));
            CPA16(bufa + O_BH + soff, whH + goff);
        }
    };
    auto stageP = [&](int c, char* buf) {
        const int j0 = c * 64;
        ull wd = mrow[j0 >> 6];
        const float* s2p = s2B + j0 + jq * 8;
        uint32_t base = (uint32_t)(prow * 128 + jq * 16);
#pragma unroll
        for (int g = 0; g < 2; ++g) {
            float4 s2v = *(const float4*)(s2p + g * 4);
            float sv[4] = {s2v.x, s2v.y, s2v.z, s2v.w};
            float p[4];
#pragma unroll
            for (int e = 0; e < 4; ++e) {
                int jl = jq * 8 + g * 4 + e;
                float x = s1r + sv[e];
                x = fmaxf(x, 0.2f * x);
                float mkf = (float)((wd >> jl) & 1ull);
                p[e] = mkf * fexp(fmaxf(x - Mi, -80.f));
                zacc += p[e];
            }
            uint32_t h01 = packh2(p[0], p[1]);
            uint32_t h23 = packh2(p[2], p[3]);
            *(uint2*)(buf + O_PH + SWZ128(base + g * 8)) = make_uint2(h01, h23);
        }
    };

    stageB(0, smb);
    CPCOMMIT();
    stageP(0, sm);

    for (int c = 0; c < 32; ++c) {
        const int p = c & 1;
        const uint32_t bufa = smb + p * BUFSZ;
        char* bufn = sm + (p ^ 1) * BUFSZ;

        if (c < 31) {
            stageB(c + 1, smb + (p ^ 1) * BUFSZ);
            CPCOMMIT();
            stageP(c + 1, bufn);
            CPWAIT1();
        } else {
            CPWAIT0();
        }
        __syncthreads();

#pragma unroll
        for (int k16 = 0; k16 < 4; ++k16) {
            uint32_t ah[4];
            ldsm4(ah, bufa + O_PH + SWZ128(a_l + (uint32_t)(k16 * 32)));
#pragma unroll
            for (int nt2 = 0; nt2 < 4; ++nt2) {
                uint32_t bo = SWZ128(b_l + (uint32_t)(nt2 * 2048 + k16 * 32));
                uint32_t bh[4];
                ldsm4(bh, bufa + O_BH + bo);
                mmaf16(acc[nt2 * 2 + 0], ah, bh);
                mmaf16(acc[nt2 * 2 + 1], ah, bh + 2);
            }
        }
        __syncthreads();
    }

    // ---- Z reduce: 8 threads (jq) share prow; lanes 8-aligned ----
    float* zs = (float*)sm;
    zacc += __shfl_xor_sync(0xffffffffu, zacc, 1);
    zacc += __shfl_xor_sync(0xffffffffu, zacc, 2);
    zacc += __shfl_xor_sync(0xffffffffu, zacc, 4);
    if (jq == 0) zs[prow] = 1.0f / zacc;    // diag in mask -> zacc > 0
    __syncthreads();

    // ---- epilogue: normalize + ELU + store ----
    const int tq = lane >> 2, tr = lane & 3;
    {
        int il = wm * 16 + tq;
        float iz0 = zs[il], iz1 = zs[il + 8];
        int i = i0 + il;
        float* op0 = out + ((size_t)bz * NN + i) * FF + wn * 64 + tr * 2;
#pragma unroll
        for (int nt = 0; nt < 8; ++nt) {
            float2 v0 = make_float2(elu1(acc[nt][0] * iz0),
                                    elu1(acc[nt][1] * iz0));
            float2 v1 = make_float2(elu1(acc[nt][2] * iz1),
                                    elu1(acc[nt][3] * iz1));
            *(float2*)(op0 + nt * 8) = v0;
            *(float2*)(op0 + nt * 8 + 8 * FF) = v1;
        }
    }
}

// ========================================================================
extern "C" void kernel_launch(void* const* d_in, const int* in_sizes, int n_in,
                              void* d_out, int out_size) {
    const float* h   = (const float*)d_in[0];
    const int*   adj = (const int*)d_in[1];
    const float* W   = (const float*)d_in[2];
    const float* a   = (const float*)d_in[3];
    float* out = (float*)d_out;

    cudaFuncSetAttribute(k_gemm1, cudaFuncAttributeMaxDynamicSharedMemorySize, 66560);
    cudaFuncSetAttribute(k_attn, cudaFuncAttributeMaxDynamicSharedMemorySize, 2 * BUFSZ);

    k_packW<<<FF, FF>>>(W);
    k_mask <<<NN * 128 / 256, 256>>>(adj);
    k_gemm1<<<dim3(128, 2), 256, 66560>>>(h, a);
    k_smax <<<BB, 256>>>();
    k_attn <<<dim3(NN / 32, BB), 256, 2 * BUFSZ>>>(out);
}

// round 10
// speedup vs baseline: 1.7870x; 1.7870x over previous
#include <cuda_runtime.h>
#include <cuda_fp16.h>
#include <cstdint>

#define BB 8
#define NN 2048
#define FF 256

// ---- scratch ----
__device__ unsigned short g_WhTh[BB * FF * NN];   // f16 hi, [b][f][j], 8 MB
__device__ unsigned short g_WtH[FF * FF];         // f16 W^T hi [fout][fin]
__device__ unsigned short g_WtL[FF * FF];         // f16 W^T lo
__device__ float g_s1[BB * NN];
__device__ float g_s2[BB * NN];
__device__ float g_smax[BB];
__device__ unsigned long long g_mask[NN * 32];

typedef unsigned long long ull;

#define L2E 1.4426950408889634f

// MUFU-based exp2
__device__ __forceinline__ float ex2(float x) {
    float r;
    asm("ex2.approx.ftz.f32 %0, %1;" : "=f"(r) : "f"(x));
    return r;
}
__device__ __forceinline__ float elu1(float x) {
    return x > 0.f ? x : ex2(x * L2E) - 1.f;
}
__device__ __forceinline__ uint32_t packh2r(float a, float b, float& ra, float& rb) {
    __half ha = __float2half_rn(a), hb = __float2half_rn(b);
    ra = a - __half2float(ha);
    rb = b - __half2float(hb);
    __half2 h2 = __halves2half2(ha, hb);
    return reinterpret_cast<uint32_t&>(h2);
}
__device__ __forceinline__ uint32_t packh2(float a, float b) {
    __half2 h2 = __floats2half2_rn(a, b);
    return reinterpret_cast<uint32_t&>(h2);
}

#define SWZ128(o) ((o) ^ (((o) >> 3) & 0x70))

// ---- mma.sync / ldmatrix / cp.async ----
__device__ __forceinline__ void ldsm4(uint32_t* r, uint32_t a) {
    asm volatile("ldmatrix.sync.aligned.m8n8.x4.shared.b16 {%0,%1,%2,%3}, [%4];"
        : "=r"(r[0]), "=r"(r[1]), "=r"(r[2]), "=r"(r[3]) : "r"(a));
}
__device__ __forceinline__ void mmaf16(float* c, const uint32_t* a, const uint32_t* b) {
    asm volatile(
        "mma.sync.aligned.m16n8k16.row.col.f32.f16.f16.f32 "
        "{%0,%1,%2,%3}, {%4,%5,%6,%7}, {%8,%9}, {%0,%1,%2,%3};"
        : "+f"(c[0]), "+f"(c[1]), "+f"(c[2]), "+f"(c[3])
        : "r"(a[0]), "r"(a[1]), "r"(a[2]), "r"(a[3]), "r"(b[0]), "r"(b[1]));
}
__device__ __forceinline__ uint32_t smem_u32(const void* p) {
    uint32_t a;
    asm("{ .reg .u64 t; cvta.to.shared.u64 t, %1; cvt.u32.u64 %0, t; }"
        : "=r"(a) : "l"(p));
    return a;
}
#define CPA16(dst, src) asm volatile( \
    "cp.async.cg.shared.global [%0], [%1], 16;" :: "r"(dst), "l"(src))
#define CPCOMMIT() asm volatile("cp.async.commit_group;" ::: "memory")
#define CPWAIT1() asm volatile("cp.async.wait_group 1;" ::: "memory")
#define CPWAIT0() asm volatile("cp.async.wait_group 0;" ::: "memory")

// ========================================================================
// Kernel 0: pack W -> f16 hi/lo, transposed [fout][fin]
// ========================================================================
__global__ void k_packW(const float* __restrict__ W) {
    const int fo = blockIdx.x, fi = threadIdx.x;
    float v = W[fi * FF + fo];
    float r0, dummy;
    uint32_t hp = packh2r(v, 0.f, r0, dummy);
    g_WtH[fo * FF + fi] = (unsigned short)(hp & 0xffff);
    g_WtL[fo * FF + fi] = (unsigned short)(packh2(r0, 0.f) & 0xffff);
}

// ========================================================================
// Kernel 1: pack mask bits + zero s1/s2
// ========================================================================
__global__ void __launch_bounds__(256)
k_mask(const int* __restrict__ adj) {
    const int gid = blockIdx.x * 256 + threadIdx.x;
    if (gid < BB * NN) { g_s1[gid] = 0.f; g_s2[gid] = 0.f; }
    const int i = gid >> 7, seg = gid & 127;
    const int4* src = (const int4*)(adj + (size_t)i * NN + seg * 16);
    unsigned int m = 0;
#pragma unroll
    for (int q = 0; q < 4; ++q) {
        int4 v = src[q];
        if (v.x > 0) m |= 1u << (q * 4 + 0);
        if (v.y > 0) m |= 1u << (q * 4 + 1);
        if (v.z > 0) m |= 1u << (q * 4 + 2);
        if (v.w > 0) m |= 1u << (q * 4 + 3);
    }
    int d = i - seg * 16;
    if (d >= 0 && d < 16) m |= 1u << d;
    ((unsigned short*)g_mask)[gid] = (unsigned short)m;
}

// ========================================================================
// Kernel 2 (mma): Wh = h @ W (3-term f16 split, fp32-accurate).
// ========================================================================
#define G_AH 0
#define G_AL 16384
#define G_BH 32768
#define G_BL 49152

__global__ void __launch_bounds__(256)
k_gemm1(const float* __restrict__ h, const float* __restrict__ a) {
    extern __shared__ __align__(1024) char sm[];
    const uint32_t smb = smem_u32(sm);
    __shared__ float as1[128], as2[128];
    const int i0g = blockIdx.x * 128, fy = blockIdx.y;
    const int b = i0g >> 11, jb = i0g & (NN - 1);
    const int t = threadIdx.x, wid = t >> 5, lane = t & 31;
    const int wm = wid & 3, wn = wid >> 2;

    if (t < 128) as1[t] = a[fy * 128 + t];
    else         as2[t - 128] = a[256 + fy * 128 + (t - 128)];

    const uint32_t a_l = (uint32_t)(((wm * 32 + (lane & 15)) << 7) | ((lane >> 4) << 4));
    const uint32_t b_l = (uint32_t)(((wn * 64 + ((lane >> 4) << 3) + (lane & 7)) << 7)
                                    | (((lane >> 3) & 1) << 4));

    float acc[2][8][4];
#pragma unroll
    for (int mt = 0; mt < 2; ++mt)
#pragma unroll
        for (int nt = 0; nt < 8; ++nt)
#pragma unroll
            for (int e = 0; e < 4; ++e) acc[mt][nt][e] = 0.f;

    const int arow = t >> 1, akh = t & 1;
    const float* hp = h + ((size_t)(i0g + arow)) * FF + akh * 32;

    for (int c = 0; c < 4; ++c) {
        const int k0 = c * 64;
#pragma unroll
        for (int q = 0; q < 4; ++q) {
            int idx = t + q * 256;
            int f = idx >> 3, seg = idx & 7;
            const unsigned short* sH = g_WtH + (size_t)(fy * 128 + f) * FF + k0 + seg * 8;
            const unsigned short* sL = g_WtL + (size_t)(fy * 128 + f) * FF + k0 + seg * 8;
            uint32_t soff = SWZ128((uint32_t)(f * 128 + seg * 16));
            CPA16(smb + G_BH + soff, sH);
            CPA16(smb + G_BL + soff, sL);
        }
        CPCOMMIT();
#pragma unroll
        for (int q = 0; q < 8; ++q) {
            float4 v = *(const float4*)(hp + k0 + q * 4);
            float r0, r1, r2, r3;
            uint32_t h01 = packh2r(v.x, v.y, r0, r1);
            uint32_t h23 = packh2r(v.z, v.w, r2, r3);
            uint32_t l01 = packh2(r0, r1);
            uint32_t l23 = packh2(r2, r3);
            uint32_t base = (uint32_t)(arow * 128 + (akh * 32 + q * 4) * 2);
            uint32_t so = SWZ128(base);
            *(uint2*)(sm + G_AH + so) = make_uint2(h01, h23);
            *(uint2*)(sm + G_AL + so) = make_uint2(l01, l23);
        }
        CPWAIT0();
        __syncthreads();

#pragma unroll
        for (int k16 = 0; k16 < 4; ++k16) {
            uint32_t ahh[2][4], ahl[2][4];
#pragma unroll
            for (int mt = 0; mt < 2; ++mt) {
                uint32_t ao = SWZ128(a_l + (uint32_t)(mt * 2048 + k16 * 32));
                ldsm4(ahh[mt], smb + G_AH + ao);
                ldsm4(ahl[mt], smb + G_AL + ao);
            }
#pragma unroll
            for (int nt2 = 0; nt2 < 4; ++nt2) {
                uint32_t bo = SWZ128(b_l + (uint32_t)(nt2 * 2048 + k16 * 32));
                uint32_t bh[4], bl[4];
                ldsm4(bh, smb + G_BH + bo);
                ldsm4(bl, smb + G_BL + bo);
#pragma unroll
                for (int mt = 0; mt < 2; ++mt) {
                    mmaf16(acc[mt][nt2 * 2 + 0], ahh[mt], bh);
                    mmaf16(acc[mt][nt2 * 2 + 1], ahh[mt], bh + 2);
                    mmaf16(acc[mt][nt2 * 2 + 0], ahl[mt], bh);
                    mmaf16(acc[mt][nt2 * 2 + 1], ahl[mt], bh + 2);
                    mmaf16(acc[mt][nt2 * 2 + 0], ahh[mt], bl);
                    mmaf16(acc[mt][nt2 * 2 + 1], ahh[mt], bl + 2);
                }
            }
        }
        __syncthreads();
    }

    // ---- epilogue: transpose via smem (fp32 [f][i], stride 130) ----
    float* ts = (float*)sm;
    const int tq = lane >> 2, tr = lane & 3;
#pragma unroll
    for (int mt = 0; mt < 2; ++mt) {
        int i_l = wm * 32 + mt * 16 + tq;
#pragma unroll
        for (int nt = 0; nt < 8; ++nt) {
            int f_l = wn * 64 + nt * 8 + tr * 2;
            ts[f_l * 130 + i_l]           = acc[mt][nt][0];
            ts[(f_l + 1) * 130 + i_l]     = acc[mt][nt][1];
            ts[f_l * 130 + i_l + 8]       = acc[mt][nt][2];
            ts[(f_l + 1) * 130 + i_l + 8] = acc[mt][nt][3];
        }
    }
    __syncthreads();

    {
        const int i_l = t >> 1, fh = t & 1;
        float s1p = 0.f, s2p = 0.f;
#pragma unroll 8
        for (int f = 0; f < 64; ++f) {
            int fl = fh * 64 + f;
            float v = ts[fl * 130 + i_l];
            s1p += v * as1[fl];
            s2p += v * as2[fl];
        }
        s1p += __shfl_xor_sync(0xffffffffu, s1p, 1);
        s2p += __shfl_xor_sync(0xffffffffu, s2p, 1);
        if (fh == 0) {
            atomicAdd(&g_s1[b * NN + jb + i_l], s1p);
            atomicAdd(&g_s2[b * NN + jb + i_l], s2p);
        }
    }

    {
        const int fl = t >> 1, half = t & 1;
        unsigned short* dst = g_WhTh + ((size_t)(b * FF) + fy * 128 + fl) * NN
                              + jb + half * 64;
        const float* src = ts + fl * 130 + half * 64;
#pragma unroll
        for (int q = 0; q < 8; ++q) {
            float v0 = src[q * 8 + 0], v1 = src[q * 8 + 1];
            float v2 = src[q * 8 + 2], v3 = src[q * 8 + 3];
            float v4 = src[q * 8 + 4], v5 = src[q * 8 + 5];
            float v6 = src[q * 8 + 6], v7 = src[q * 8 + 7];
            uint4 hv = make_uint4(packh2(v0, v1), packh2(v2, v3),
                                  packh2(v4, v5), packh2(v6, v7));
            *(uint4*)(dst + q * 8) = hv;
        }
    }
}

// ========================================================================
// Kernel 3: per-batch unmasked max of s2
// ========================================================================
__global__ void __launch_bounds__(256)
k_smax() {
    const int b = blockIdx.x, t = threadIdx.x;
    __shared__ float red[8];
    float mx = -3e38f;
#pragma unroll
    for (int q = 0; q < 8; ++q)
        mx = fmaxf(mx, g_s2[b * NN + t + q * 256]);
#pragma unroll
    for (int off = 16; off > 0; off >>= 1)
        mx = fmaxf(mx, __shfl_xor_sync(0xffffffffu, mx, off));
    if ((t & 31) == 0) red[t >> 5] = mx;
    __syncthreads();
    if (t == 0) {
        float v = red[0];
        for (int w = 1; w < 8; ++w) v = fmaxf(v, red[w]);
        g_smax[b] = v;
    }
}

// ========================================================================
// Kernel 4 (mma.sync f16): out = elu((P_u @ Wh) / Z), fused normalizer.
// CTA tile M=64 x N=256; 256 thr = 8 warps (2m x 4n); warp m32 x n64.
// j-chunks of 64; double-buffered 40 KB; 2 CTAs/SM.
// P weights via MUFU ex2 (exp2-domain, clamp-free).
// ========================================================================
#define BUFSZ 40960
#define O_PH 0
#define O_BH 8192

__global__ void __launch_bounds__(256, 2)
k_attn(float* __restrict__ out) {
    extern __shared__ __align__(1024) char sm[];
    const uint32_t smb = smem_u32(sm);
    const int bz = blockIdx.y, i0 = blockIdx.x * 64;
    const int t = threadIdx.x, wid = t >> 5, lane = t & 31;
    const int wm = wid & 1, wn = wid >> 1;

    const int prow = t >> 2, jq = t & 3;          // 64 rows x 16 j per thread
    const float s1r = g_s1[bz * NN + i0 + prow];
    const float smax = g_smax[bz];
    float Mx = s1r + smax;
    const float Mi = fmaxf(Mx, 0.2f * Mx);
    // exp2-domain row constants
    const float s1L = s1r * L2E;
    const float MiL = Mi * L2E;
    const ull* mrow = g_mask + (size_t)(i0 + prow) * 32;

    const unsigned short* whH = g_WhTh + (size_t)bz * FF * NN;
    const float* s2B = g_s2 + bz * NN;

    const uint32_t a_l = (uint32_t)(((wm * 32 + (lane & 15)) << 7) | ((lane >> 4) << 4));
    const uint32_t b_l = (uint32_t)(((wn * 64 + ((lane >> 4) << 3) + (lane & 7)) << 7)
                                    | (((lane >> 3) & 1) << 4));

    float acc[2][8][4];
#pragma unroll
    for (int mt = 0; mt < 2; ++mt)
#pragma unroll
        for (int nt = 0; nt < 8; ++nt)
#pragma unroll
            for (int e = 0; e < 4; ++e) acc[mt][nt][e] = 0.f;
    float zacc = 0.f;

    auto stageB = [&](int c, uint32_t bufa) {
        const int j0 = c * 64;
#pragma unroll
        for (int q = 0; q < 8; ++q) {
            int idx = t + q * 256;                 // 0..2047
            int f = idx >> 3, seg = idx & 7;
            size_t goff = (size_t)f * NN + j0 + seg * 8;
            uint32_t soff = SWZ128((uint32_t)(f * 128 + seg * 16));
            CPA16(bufa + O_BH + soff, whH + goff);
        }
    };
    auto stageP = [&](int c, char* buf) {
        const int j0 = c * 64;
        // 16 mask bits for this thread's j-range, 32-bit ops only
        uint32_t wd16 = (uint32_t)(mrow[j0 >> 6] >> (jq * 16)) & 0xffffu;
        const float* s2p = s2B + j0 + jq * 16;
        uint32_t base = (uint32_t)(prow * 128 + jq * 32);
#pragma unroll
        for (int g = 0; g < 4; ++g) {
            float4 s2v = *(const float4*)(s2p + g * 4);
            float sv[4] = {s2v.x, s2v.y, s2v.z, s2v.w};
            float p[4];
#pragma unroll
            for (int e = 0; e < 4; ++e) {
                float xl = fmaf(sv[e], L2E, s1L);      // lrelu in exp2 domain
                xl = fmaxf(xl, 0.2f * xl);
                float ex = ex2(xl - MiL);              // exp2(-big)->0, no clamp
                p[e] = ((wd16 >> (g * 4 + e)) & 1u) ? ex : 0.f;
                zacc += p[e];
            }
            uint32_t h01 = packh2(p[0], p[1]);
            uint32_t h23 = packh2(p[2], p[3]);
            *(uint2*)(buf + O_PH + SWZ128(base + g * 8)) = make_uint2(h01, h23);
        }
    };

    stageB(0, smb);
    CPCOMMIT();
    stageP(0, sm);

    for (int c = 0; c < 32; ++c) {
        const int p = c & 1;
        const uint32_t bufa = smb + p * BUFSZ;
        char* bufn = sm + (p ^ 1) * BUFSZ;

        if (c < 31) {
            stageB(c + 1, smb + (p ^ 1) * BUFSZ);
            CPCOMMIT();
            stageP(c + 1, bufn);
            CPWAIT1();
        } else {
            CPWAIT0();
        }
        __syncthreads();

#pragma unroll
        for (int k16 = 0; k16 < 4; ++k16) {
            uint32_t ah[2][4];
#pragma unroll
            for (int mt = 0; mt < 2; ++mt)
                ldsm4(ah[mt], bufa + O_PH +
                      SWZ128(a_l + (uint32_t)(mt * 2048 + k16 * 32)));
#pragma unroll
            for (int nt2 = 0; nt2 < 4; ++nt2) {
                uint32_t bo = SWZ128(b_l + (uint32_t)(nt2 * 2048 + k16 * 32));
                uint32_t bh[4];
                ldsm4(bh, bufa + O_BH + bo);
#pragma unroll
                for (int mt = 0; mt < 2; ++mt) {
                    mmaf16(acc[mt][nt2 * 2 + 0], ah[mt], bh);
                    mmaf16(acc[mt][nt2 * 2 + 1], ah[mt], bh + 2);
                }
            }
        }
        __syncthreads();
    }

    // ---- Z reduce: 4 threads (jq) share prow; lanes 4-aligned ----
    float* zs = (float*)sm;
    zacc += __shfl_xor_sync(0xffffffffu, zacc, 1);
    zacc += __shfl_xor_sync(0xffffffffu, zacc, 2);
    if (jq == 0) zs[prow] = 1.0f / zacc;    // diag in mask -> zacc > 0
    __syncthreads();

    // ---- epilogue: normalize + ELU + store ----
    const int tq = lane >> 2, tr = lane & 3;
#pragma unroll
    for (int mt = 0; mt < 2; ++mt) {
        int il = wm * 32 + mt * 16 + tq;
        float iz0 = zs[il], iz1 = zs[il + 8];
        int i = i0 + il;
        float* op0 = out + ((size_t)bz * NN + i) * FF + wn * 64 + tr * 2;
#pragma unroll
        for (int nt = 0; nt < 8; ++nt) {
            float2 v0 = make_float2(elu1(acc[mt][nt][0] * iz0),
                                    elu1(acc[mt][nt][1] * iz0));
            float2 v1 = make_float2(elu1(acc[mt][nt][2] * iz1),
                                    elu1(acc[mt][nt][3] * iz1));
            *(float2*)(op0 + nt * 8) = v0;
            *(float2*)(op0 + nt * 8 + 8 * FF) = v1;
        }
    }
}

// ========================================================================
extern "C" void kernel_launch(void* const* d_in, const int* in_sizes, int n_in,
                              void* d_out, int out_size) {
    const float* h   = (const float*)d_in[0];
    const int*   adj = (const int*)d_in[1];
    const float* W   = (const float*)d_in[2];
    const float* a   = (const float*)d_in[3];
    float* out = (float*)d_out;

    cudaFuncSetAttribute(k_gemm1, cudaFuncAttributeMaxDynamicSharedMemorySize, 66560);
    cudaFuncSetAttribute(k_attn, cudaFuncAttributeMaxDynamicSharedMemorySize, 2 * BUFSZ);

    k_packW<<<FF, FF>>>(W);
    k_mask <<<NN * 128 / 256, 256>>>(adj);
    k_gemm1<<<dim3(128, 2), 256, 66560>>>(h, a);
    k_smax <<<BB, 256>>>();
    k_attn <<<dim3(NN / 64, BB), 256, 2 * BUFSZ>>>(out);
}

// round 11
// speedup vs baseline: 2.0009x; 1.1197x over previous
#include <cuda_runtime.h>
#include <cuda_fp16.h>
#include <cstdint>

#define BB 8
#define NN 2048
#define FF 256

// ---- scratch ----
__device__ unsigned short g_WhTh[BB * FF * NN];   // f16 hi, [b][f][j], 8 MB
__device__ unsigned short g_WtH[FF * FF];         // f16 W^T [fout][fin]
__device__ float g_s1[BB * NN];
__device__ float g_s2[BB * NN];
__device__ float g_smax[BB];
__device__ unsigned long long g_mask[NN * 32];

typedef unsigned long long ull;

#define L2E 1.4426950408889634f

__device__ __forceinline__ float ex2(float x) {
    float r;
    asm("ex2.approx.ftz.f32 %0, %1;" : "=f"(r) : "f"(x));
    return r;
}
__device__ __forceinline__ float elu1(float x) {
    return x > 0.f ? x : ex2(x * L2E) - 1.f;
}
__device__ __forceinline__ uint32_t packh2(float a, float b) {
    __half2 h2 = __floats2half2_rn(a, b);
    return reinterpret_cast<uint32_t&>(h2);
}

#define SWZ128(o) ((o) ^ (((o) >> 3) & 0x70))

// ---- mma.sync / ldmatrix / cp.async ----
__device__ __forceinline__ void ldsm4(uint32_t* r, uint32_t a) {
    asm volatile("ldmatrix.sync.aligned.m8n8.x4.shared.b16 {%0,%1,%2,%3}, [%4];"
        : "=r"(r[0]), "=r"(r[1]), "=r"(r[2]), "=r"(r[3]) : "r"(a));
}
__device__ __forceinline__ void mmaf16(float* c, const uint32_t* a, const uint32_t* b) {
    asm volatile(
        "mma.sync.aligned.m16n8k16.row.col.f32.f16.f16.f32 "
        "{%0,%1,%2,%3}, {%4,%5,%6,%7}, {%8,%9}, {%0,%1,%2,%3};"
        : "+f"(c[0]), "+f"(c[1]), "+f"(c[2]), "+f"(c[3])
        : "r"(a[0]), "r"(a[1]), "r"(a[2]), "r"(a[3]), "r"(b[0]), "r"(b[1]));
}
__device__ __forceinline__ uint32_t smem_u32(const void* p) {
    uint32_t a;
    asm("{ .reg .u64 t; cvta.to.shared.u64 t, %1; cvt.u32.u64 %0, t; }"
        : "=r"(a) : "l"(p));
    return a;
}
#define CPA16(dst, src) asm volatile( \
    "cp.async.cg.shared.global [%0], [%1], 16;" :: "r"(dst), "l"(src))
#define CPCOMMIT() asm volatile("cp.async.commit_group;" ::: "memory")
#define CPWAIT1() asm volatile("cp.async.wait_group 1;" ::: "memory")
#define CPWAIT0() asm volatile("cp.async.wait_group 0;" ::: "memory")

// ========================================================================
// Kernel 0: pack W -> f16, transposed [fout][fin]
// ========================================================================
__global__ void k_packW(const float* __restrict__ W) {
    const int fo = blockIdx.x, fi = threadIdx.x;
    g_WtH[fo * FF + fi] = (unsigned short)(packh2(W[fi * FF + fo], 0.f) & 0xffff);
}

// ========================================================================
// Kernel 1: pack mask bits via warp ballot (coalesced) + zero s1/s2.
// One warp per row; lanes read 32 consecutive ints; unroll-8 for MLP.
// Grid 256 x 256 thr = 2048 warps = 2048 rows.
// ========================================================================
__global__ void __launch_bounds__(256)
k_mask(const int* __restrict__ adj) {
    const int gid = blockIdx.x * 256 + threadIdx.x;
    if (gid < BB * NN) { g_s1[gid] = 0.f; g_s2[gid] = 0.f; }
    const int row = gid >> 5, lane = gid & 31;
    const int* rp = adj + (size_t)row * NN;
    uint32_t* dst = ((uint32_t*)g_mask) + row * 64;
#pragma unroll 2
    for (int it0 = 0; it0 < 64; it0 += 8) {
        int v[8];
#pragma unroll
        for (int q = 0; q < 8; ++q)
            v[q] = rp[(it0 + q) * 32 + lane];
#pragma unroll
        for (int q = 0; q < 8; ++q) {
            int j = (it0 + q) * 32 + lane;
            uint32_t w = __ballot_sync(0xffffffffu, (v[q] > 0) || (j == row));
            if (lane == 0) dst[it0 + q] = w;
        }
    }
}

// ========================================================================
// Kernel 2 (mma): Wh = h @ W, single-term f16 (h,W rounded to f16).
// Emits WhT f16 [b][f][j] + s1/s2 fp32 (from fp32 accumulators).
// Grid (128, 2): 128 i x 128 f per CTA; K=256 in 4 chunks of 64.
// ========================================================================
#define G_A 0
#define G_B 16384

__global__ void __launch_bounds__(256)
k_gemm1(const float* __restrict__ h, const float* __restrict__ a) {
    extern __shared__ __align__(1024) char sm[];
    const uint32_t smb = smem_u32(sm);
    __shared__ float as1[128], as2[128];
    const int i0g = blockIdx.x * 128, fy = blockIdx.y;
    const int b = i0g >> 11, jb = i0g & (NN - 1);
    const int t = threadIdx.x, wid = t >> 5, lane = t & 31;
    const int wm = wid & 3, wn = wid >> 2;

    if (t < 128) as1[t] = a[fy * 128 + t];
    else         as2[t - 128] = a[256 + fy * 128 + (t - 128)];

    const uint32_t a_l = (uint32_t)(((wm * 32 + (lane & 15)) << 7) | ((lane >> 4) << 4));
    const uint32_t b_l = (uint32_t)(((wn * 64 + ((lane >> 4) << 3) + (lane & 7)) << 7)
                                    | (((lane >> 3) & 1) << 4));

    float acc[2][8][4];
#pragma unroll
    for (int mt = 0; mt < 2; ++mt)
#pragma unroll
        for (int nt = 0; nt < 8; ++nt)
#pragma unroll
            for (int e = 0; e < 4; ++e) acc[mt][nt][e] = 0.f;

    const int arow = t >> 1, akh = t & 1;
    const float* hp = h + ((size_t)(i0g + arow)) * FF + akh * 32;

    for (int c = 0; c < 4; ++c) {
        const int k0 = c * 64;
        // B: WtH [128 f][64 k] via cp.async
#pragma unroll
        for (int q = 0; q < 4; ++q) {
            int idx = t + q * 256;
            int f = idx >> 3, seg = idx & 7;
            const unsigned short* sH = g_WtH + (size_t)(fy * 128 + f) * FF + k0 + seg * 8;
            CPA16(smb + G_B + SWZ128((uint32_t)(f * 128 + seg * 16)), sH);
        }
        CPCOMMIT();
        // A: h fp32 -> f16
#pragma unroll
        for (int q = 0; q < 8; ++q) {
            float4 v = *(const float4*)(hp + k0 + q * 4);
            uint32_t h01 = packh2(v.x, v.y);
            uint32_t h23 = packh2(v.z, v.w);
            uint32_t base = (uint32_t)(arow * 128 + (akh * 32 + q * 4) * 2);
            *(uint2*)(sm + G_A + SWZ128(base)) = make_uint2(h01, h23);
        }
        CPWAIT0();
        __syncthreads();

#pragma unroll
        for (int k16 = 0; k16 < 4; ++k16) {
            uint32_t ah[2][4];
#pragma unroll
            for (int mt = 0; mt < 2; ++mt)
                ldsm4(ah[mt], smb + G_A +
                      SWZ128(a_l + (uint32_t)(mt * 2048 + k16 * 32)));
#pragma unroll
            for (int nt2 = 0; nt2 < 4; ++nt2) {
                uint32_t bo = SWZ128(b_l + (uint32_t)(nt2 * 2048 + k16 * 32));
                uint32_t bh[4];
                ldsm4(bh, smb + G_B + bo);
#pragma unroll
                for (int mt = 0; mt < 2; ++mt) {
                    mmaf16(acc[mt][nt2 * 2 + 0], ah[mt], bh);
                    mmaf16(acc[mt][nt2 * 2 + 1], ah[mt], bh + 2);
                }
            }
        }
        __syncthreads();
    }

    // ---- epilogue: transpose via smem (fp32 [f][i], stride 130) ----
    float* ts = (float*)sm;
    const int tq = lane >> 2, tr = lane & 3;
#pragma unroll
    for (int mt = 0; mt < 2; ++mt) {
        int i_l = wm * 32 + mt * 16 + tq;
#pragma unroll
        for (int nt = 0; nt < 8; ++nt) {
            int f_l = wn * 64 + nt * 8 + tr * 2;
            ts[f_l * 130 + i_l]           = acc[mt][nt][0];
            ts[(f_l + 1) * 130 + i_l]     = acc[mt][nt][1];
            ts[f_l * 130 + i_l + 8]       = acc[mt][nt][2];
            ts[(f_l + 1) * 130 + i_l + 8] = acc[mt][nt][3];
        }
    }
    __syncthreads();

    {
        const int i_l = t >> 1, fh = t & 1;
        float s1p = 0.f, s2p = 0.f;
#pragma unroll 8
        for (int f = 0; f < 64; ++f) {
            int fl = fh * 64 + f;
            float v = ts[fl * 130 + i_l];
            s1p += v * as1[fl];
            s2p += v * as2[fl];
        }
        s1p += __shfl_xor_sync(0xffffffffu, s1p, 1);
        s2p += __shfl_xor_sync(0xffffffffu, s2p, 1);
        if (fh == 0) {
            atomicAdd(&g_s1[b * NN + jb + i_l], s1p);
            atomicAdd(&g_s2[b * NN + jb + i_l], s2p);
        }
    }

    {
        const int fl = t >> 1, half = t & 1;
        unsigned short* dst = g_WhTh + ((size_t)(b * FF) + fy * 128 + fl) * NN
                              + jb + half * 64;
        const float* src = ts + fl * 130 + half * 64;
#pragma unroll
        for (int q = 0; q < 8; ++q) {
            float v0 = src[q * 8 + 0], v1 = src[q * 8 + 1];
            float v2 = src[q * 8 + 2], v3 = src[q * 8 + 3];
            float v4 = src[q * 8 + 4], v5 = src[q * 8 + 5];
            float v6 = src[q * 8 + 6], v7 = src[q * 8 + 7];
            uint4 hv = make_uint4(packh2(v0, v1), packh2(v2, v3),
                                  packh2(v4, v5), packh2(v6, v7));
            *(uint4*)(dst + q * 8) = hv;
        }
    }
}

// ========================================================================
// Kernel 3: per-batch unmasked max of s2
// ========================================================================
__global__ void __launch_bounds__(256)
k_smax() {
    const int b = blockIdx.x, t = threadIdx.x;
    __shared__ float red[8];
    float mx = -3e38f;
#pragma unroll
    for (int q = 0; q < 8; ++q)
        mx = fmaxf(mx, g_s2[b * NN + t + q * 256]);
#pragma unroll
    for (int off = 16; off > 0; off >>= 1)
        mx = fmaxf(mx, __shfl_xor_sync(0xffffffffu, mx, off));
    if ((t & 31) == 0) red[t >> 5] = mx;
    __syncthreads();
    if (t == 0) {
        float v = red[0];
        for (int w = 1; w < 8; ++w) v = fmaxf(v, red[w]);
        g_smax[b] = v;
    }
}

// ========================================================================
// Kernel 4 (mma.sync f16): out = elu((P_u @ Wh) / Z), fused normalizer.
// CTA tile M=64 x N=256; 256 thr = 8 warps (2m x 4n); warp m32 x n64.
// j-chunks of 64; double-buffered 40 KB; 2 CTAs/SM; MUFU ex2 P weights.
// ========================================================================
#define BUFSZ 40960
#define O_PH 0
#define O_BH 8192

__global__ void __launch_bounds__(256, 2)
k_attn(float* __restrict__ out) {
    extern __shared__ __align__(1024) char sm[];
    const uint32_t smb = smem_u32(sm);
    const int bz = blockIdx.y, i0 = blockIdx.x * 64;
    const int t = threadIdx.x, wid = t >> 5, lane = t & 31;
    const int wm = wid & 1, wn = wid >> 1;

    const int prow = t >> 2, jq = t & 3;          // 64 rows x 16 j per thread
    const float s1r = g_s1[bz * NN + i0 + prow];
    const float smax = g_smax[bz];
    float Mx = s1r + smax;
    const float Mi = fmaxf(Mx, 0.2f * Mx);
    const float s1L = s1r * L2E;
    const float MiL = Mi * L2E;
    const ull* mrow = g_mask + (size_t)(i0 + prow) * 32;

    const unsigned short* whH = g_WhTh + (size_t)bz * FF * NN;
    const float* s2B = g_s2 + bz * NN;

    const uint32_t a_l = (uint32_t)(((wm * 32 + (lane & 15)) << 7) | ((lane >> 4) << 4));
    const uint32_t b_l = (uint32_t)(((wn * 64 + ((lane >> 4) << 3) + (lane & 7)) << 7)
                                    | (((lane >> 3) & 1) << 4));

    float acc[2][8][4];
#pragma unroll
    for (int mt = 0; mt < 2; ++mt)
#pragma unroll
        for (int nt = 0; nt < 8; ++nt)
#pragma unroll
            for (int e = 0; e < 4; ++e) acc[mt][nt][e] = 0.f;
    float zacc = 0.f;

    auto stageB = [&](int c, uint32_t bufa) {
        const int j0 = c * 64;
#pragma unroll
        for (int q = 0; q < 8; ++q) {
            int idx = t + q * 256;
            int f = idx >> 3, seg = idx & 7;
            size_t goff = (size_t)f * NN + j0 + seg * 8;
            CPA16(bufa + O_BH + SWZ128((uint32_t)(f * 128 + seg * 16)), whH + goff);
        }
    };
    auto stageP = [&](int c, char* buf) {
        const int j0 = c * 64;
        uint32_t wd16 = (uint32_t)(mrow[j0 >> 6] >> (jq * 16)) & 0xffffu;
        const float* s2p = s2B + j0 + jq * 16;
        uint32_t base = (uint32_t)(prow * 128 + jq * 32);
#pragma unroll
        for (int g = 0; g < 4; ++g) {
            float4 s2v = *(const float4*)(s2p + g * 4);
            float sv[4] = {s2v.x, s2v.y, s2v.z, s2v.w};
            float p[4];
#pragma unroll
            for (int e = 0; e < 4; ++e) {
                float xl = fmaf(sv[e], L2E, s1L);
                xl = fmaxf(xl, 0.2f * xl);
                float ex = ex2(xl - MiL);
                p[e] = ((wd16 >> (g * 4 + e)) & 1u) ? ex : 0.f;
                zacc += p[e];
            }
            uint32_t h01 = packh2(p[0], p[1]);
            uint32_t h23 = packh2(p[2], p[3]);
            *(uint2*)(buf + O_PH + SWZ128(base + g * 8)) = make_uint2(h01, h23);
        }
    };

    stageB(0, smb);
    CPCOMMIT();
    stageP(0, sm);

    for (int c = 0; c < 32; ++c) {
        const int p = c & 1;
        const uint32_t bufa = smb + p * BUFSZ;
        char* bufn = sm + (p ^ 1) * BUFSZ;

        if (c < 31) {
            stageB(c + 1, smb + (p ^ 1) * BUFSZ);
            CPCOMMIT();
            stageP(c + 1, bufn);
            CPWAIT1();
        } else {
            CPWAIT0();
        }
        __syncthreads();

#pragma unroll
        for (int k16 = 0; k16 < 4; ++k16) {
            uint32_t ah[2][4];
#pragma unroll
            for (int mt = 0; mt < 2; ++mt)
                ldsm4(ah[mt], bufa + O_PH +
                      SWZ128(a_l + (uint32_t)(mt * 2048 + k16 * 32)));
#pragma unroll
            for (int nt2 = 0; nt2 < 4; ++nt2) {
                uint32_t bo = SWZ128(b_l + (uint32_t)(nt2 * 2048 + k16 * 32));
                uint32_t bh[4];
                ldsm4(bh, bufa + O_BH + bo);
#pragma unroll
                for (int mt = 0; mt < 2; ++mt) {
                    mmaf16(acc[mt][nt2 * 2 + 0], ah[mt], bh);
                    mmaf16(acc[mt][nt2 * 2 + 1], ah[mt], bh + 2);
                }
            }
        }
        __syncthreads();
    }

    // ---- Z reduce: 4 threads (jq) share prow ----
    float* zs = (float*)sm;
    zacc += __shfl_xor_sync(0xffffffffu, zacc, 1);
    zacc += __shfl_xor_sync(0xffffffffu, zacc, 2);
    if (jq == 0) zs[prow] = 1.0f / zacc;
    __syncthreads();

    // ---- epilogue: normalize + ELU + store ----
    const int tq = lane >> 2, tr = lane & 3;
#pragma unroll
    for (int mt = 0; mt < 2; ++mt) {
        int il = wm * 32 + mt * 16 + tq;
        float iz0 = zs[il], iz1 = zs[il + 8];
        int i = i0 + il;
        float* op0 = out + ((size_t)bz * NN + i) * FF + wn * 64 + tr * 2;
#pragma unroll
        for (int nt = 0; nt < 8; ++nt) {
            float2 v0 = make_float2(elu1(acc[mt][nt][0] * iz0),
                                    elu1(acc[mt][nt][1] * iz0));
            float2 v1 = make_float2(elu1(acc[mt][nt][2] * iz1),
                                    elu1(acc[mt][nt][3] * iz1));
            *(float2*)(op0 + nt * 8) = v0;
            *(float2*)(op0 + nt * 8 + 8 * FF) = v1;
        }
    }
}

// ========================================================================
extern "C" void kernel_launch(void* const* d_in, const int* in_sizes, int n_in,
                              void* d_out, int out_size) {
    const float* h   = (const float*)d_in[0];
    const int*   adj = (const int*)d_in[1];
    const float* W   = (const float*)d_in[2];
    const float* a   = (const float*)d_in[3];
    float* out = (float*)d_out;

    cudaFuncSetAttribute(k_gemm1, cudaFuncAttributeMaxDynamicSharedMemorySize, 66560);
    cudaFuncSetAttribute(k_attn, cudaFuncAttributeMaxDynamicSharedMemorySize, 2 * BUFSZ);

    k_packW<<<FF, FF>>>(W);
    k_mask <<<256, 256>>>(adj);
    k_gemm1<<<dim3(128, 2), 256, 66560>>>(h, a);
    k_smax <<<BB, 256>>>();
    k_attn <<<dim3(NN / 64, BB), 256, 2 * BUFSZ>>>(out);
}